// round 1
// baseline (speedup 1.0000x reference)
#include <cuda_runtime.h>

#define NB 4
#define NC 128
#define NCI 64
#define NN 4096

// Scratch (device globals — no allocation allowed)
__device__ __align__(16) float d_theta[NB * NCI * NN]; // [b][ci][n]  (Q, d-major)
__device__ __align__(16) float d_phi[NB * NCI * NN];   // [b][ci][n]  (K, d-major)
__device__ __align__(16) float d_g[NB * NN * NCI];     // [b][n][ci]  (V, row-major)
__device__ __align__(16) float d_y[NB * NCI * NN];     // [b][ci][n]

// FFMA-only exp (MUFU would bottleneck at 0.5/cyc/SM for 67M exps).
// x <= 0 always (softmax arg). Magic-constant round + degree-5 Taylor for 2^f.
__device__ __forceinline__ float fast_exp(float x) {
    x = fmaxf(x, -60.0f);
    float t = x * 1.4426950408889634f;     // x * log2(e)
    float r = t + 12582912.0f;             // round-to-nearest via 1.5*2^23
    int   i = __float_as_int(r) - 0x4B400000;
    float f = t - (r - 12582912.0f);       // f in [-0.5, 0.5]
    float p = 1.33336e-3f;
    p = fmaf(p, f, 9.61813e-3f);
    p = fmaf(p, f, 5.550411e-2f);
    p = fmaf(p, f, 2.4022651e-1f);
    p = fmaf(p, f, 6.9314718e-1f);
    p = fmaf(p, f, 1.0f);                  // p = 2^f in [0.707, 1.414]
    return __int_as_float(__float_as_int(p) + (i << 23));
}

// ---------------------------------------------------------------------------
// Projections: out[ci][n] = sum_c w[ci][c] * x[c][n] + b[ci]
// z=0: theta(x1) -> d_theta [ci][n]; z=1: phi(x0) -> d_phi [ci][n];
// z=2: g(x0) -> d_g [n][ci]
// Static smem: ws[64][64] + xs[64][128] = 48KB, two c-half passes.
// ---------------------------------------------------------------------------
__global__ void __launch_bounds__(256) proj_kernel(
    const float* __restrict__ x0, const float* __restrict__ x1,
    const float* __restrict__ theta_w, const float* __restrict__ theta_b,
    const float* __restrict__ phi_w,   const float* __restrict__ phi_b,
    const float* __restrict__ g_w,     const float* __restrict__ g_b)
{
    __shared__ __align__(16) float ws[64 * 64];   // [c_local][ci]
    __shared__ __align__(16) float xs[64 * 128];  // [c_local][p]

    int b = blockIdx.y;
    int n0 = blockIdx.x * 128;
    int which = blockIdx.z;
    const float* w    = (which == 0) ? theta_w : ((which == 1) ? phi_w : g_w);
    const float* bias = (which == 0) ? theta_b : ((which == 1) ? phi_b : g_b);
    const float* src  = (which == 0) ? x1 : x0;

    int t = threadIdx.x;
    int tx = t & 15, ty = t >> 4;
    int ci0 = ty * 4, p0 = tx * 4;

    float acc[4][8];
#pragma unroll
    for (int i = 0; i < 4; i++)
#pragma unroll
        for (int j = 0; j < 8; j++) acc[i][j] = 0.0f;

    const float* xb = src + (size_t)b * NC * NN + n0;

    for (int h = 0; h < 2; h++) {
        if (h) __syncthreads();
        // weights: w[ci][c], c in [h*64, h*64+64) -> ws[c_local][ci]
        for (int e = t; e < 64 * 64; e += 256) {
            int ci = e >> 6, cl = e & 63;
            ws[cl * 64 + ci] = w[ci * NC + h * 64 + cl];
        }
        // x tile: x[c][n0+p] -> xs[c_local][p]
        for (int e = t; e < 64 * 128; e += 256) {
            int cl = e >> 7, p = e & 127;
            xs[cl * 128 + p] = xb[(size_t)(h * 64 + cl) * NN + p];
        }
        __syncthreads();
#pragma unroll 4
        for (int cl = 0; cl < 64; cl++) {
            float4 wv = *(const float4*)&ws[cl * 64 + ci0];
            float4 xa = *(const float4*)&xs[cl * 128 + p0];
            float4 xc = *(const float4*)&xs[cl * 128 + p0 + 64];
            float wr[4] = {wv.x, wv.y, wv.z, wv.w};
            float xr[8] = {xa.x, xa.y, xa.z, xa.w, xc.x, xc.y, xc.z, xc.w};
#pragma unroll
            for (int i = 0; i < 4; i++)
#pragma unroll
                for (int j = 0; j < 8; j++)
                    acc[i][j] = fmaf(wr[i], xr[j], acc[i][j]);
        }
    }

    if (which < 2) {
        float* out = (which == 0 ? d_theta : d_phi) + (size_t)b * NCI * NN + n0;
#pragma unroll
        for (int i = 0; i < 4; i++) {
            float bv = bias[ci0 + i];
            float4 v0 = make_float4(acc[i][0] + bv, acc[i][1] + bv,
                                    acc[i][2] + bv, acc[i][3] + bv);
            float4 v1 = make_float4(acc[i][4] + bv, acc[i][5] + bv,
                                    acc[i][6] + bv, acc[i][7] + bv);
            *(float4*)&out[(size_t)(ci0 + i) * NN + p0] = v0;
            *(float4*)&out[(size_t)(ci0 + i) * NN + p0 + 64] = v1;
        }
    } else {
        float* out = d_g + (size_t)b * NN * NCI + (size_t)n0 * NCI;
        float b0 = bias[ci0], b1 = bias[ci0 + 1], b2 = bias[ci0 + 2], b3 = bias[ci0 + 3];
#pragma unroll
        for (int j = 0; j < 8; j++) {
            int p = (j < 4) ? (p0 + j) : (p0 + 60 + j);
            float4 v = make_float4(acc[0][j] + b0, acc[1][j] + b1,
                                   acc[2][j] + b2, acc[3][j] + b3);
            *(float4*)&out[(size_t)p * NCI + ci0] = v;
        }
    }
}

// ---------------------------------------------------------------------------
// Flash attention, fp32. One block = 64 queries of one batch.
// Static smem: Qs + KP + Vs = 3 * 64*64*4 = 48KB exactly (4 CTAs/SM, 256
// blocks -> single resident wave).
// ---------------------------------------------------------------------------
__global__ void __launch_bounds__(256) attn_kernel()
{
    __shared__ __align__(16) float Qs[64 * 64]; // [d][q]
    __shared__ __align__(16) float KP[64 * 64]; // [d][k], reused as P [k][q]
    __shared__ __align__(16) float Vs[64 * 64]; // [k][d]

    int b = blockIdx.y;
    int qb = blockIdx.x * 64;
    int t = threadIdx.x;
    int tx = t & 15, ty = t >> 4;
    int q0 = ty << 2, c0 = tx << 2;

    const float* Qg = d_theta + (size_t)b * NCI * NN;
    const float* Kg = d_phi   + (size_t)b * NCI * NN;
    const float* Vg = d_g     + (size_t)b * NN * NCI;

    // load Q tile (d-major, contiguous rows -> conflict-free)
#pragma unroll
    for (int e = t; e < 1024; e += 256) {
        int d = e >> 4, q4 = (e & 15) << 2;
        *(float4*)&Qs[d * 64 + q4] = *(const float4*)&Qg[(size_t)d * NN + qb + q4];
    }

    float m[4], l[4], o[4][4];
#pragma unroll
    for (int i = 0; i < 4; i++) {
        m[i] = -1e30f; l[i] = 0.0f;
#pragma unroll
        for (int j = 0; j < 4; j++) o[i][j] = 0.0f;
    }

    for (int kb = 0; kb < NN; kb += 64) {
#pragma unroll
        for (int e = t; e < 1024; e += 256) {
            int r = e >> 4, c4 = (e & 15) << 2;
            *(float4*)&KP[r * 64 + c4] = *(const float4*)&Kg[(size_t)r * NN + kb + c4];
        }
#pragma unroll
        for (int e = t; e < 1024; e += 256) {
            int k = e >> 4, d4 = (e & 15) << 2;
            *(float4*)&Vs[k * 64 + d4] = *(const float4*)&Vg[(size_t)(kb + k) * NCI + d4];
        }
        __syncthreads();

        // S = Q^T K  (4x4 micro-tile per thread)
        float s[4][4];
#pragma unroll
        for (int i = 0; i < 4; i++)
#pragma unroll
            for (int j = 0; j < 4; j++) s[i][j] = 0.0f;
#pragma unroll 8
        for (int d = 0; d < 64; d++) {
            float4 qv = *(const float4*)&Qs[d * 64 + q0];
            float4 kv = *(const float4*)&KP[d * 64 + c0];
            float qr[4] = {qv.x, qv.y, qv.z, qv.w};
            float kr[4] = {kv.x, kv.y, kv.z, kv.w};
#pragma unroll
            for (int i = 0; i < 4; i++)
#pragma unroll
                for (int j = 0; j < 4; j++)
                    s[i][j] = fmaf(qr[i], kr[j], s[i][j]);
        }

        // online softmax (row reductions over the 16 tx lanes)
#pragma unroll
        for (int i = 0; i < 4; i++) {
            float tm = fmaxf(fmaxf(s[i][0], s[i][1]), fmaxf(s[i][2], s[i][3]));
            tm = fmaxf(tm, __shfl_xor_sync(0xffffffffu, tm, 1));
            tm = fmaxf(tm, __shfl_xor_sync(0xffffffffu, tm, 2));
            tm = fmaxf(tm, __shfl_xor_sync(0xffffffffu, tm, 4));
            tm = fmaxf(tm, __shfl_xor_sync(0xffffffffu, tm, 8));
            float nm = fmaxf(m[i], tm);
            float sc = fast_exp(m[i] - nm);
            float rs = 0.0f;
#pragma unroll
            for (int j = 0; j < 4; j++) {
                s[i][j] = fast_exp(s[i][j] - nm);
                rs += s[i][j];
            }
            rs += __shfl_xor_sync(0xffffffffu, rs, 1);
            rs += __shfl_xor_sync(0xffffffffu, rs, 2);
            rs += __shfl_xor_sync(0xffffffffu, rs, 4);
            rs += __shfl_xor_sync(0xffffffffu, rs, 8);
            l[i] = fmaf(l[i], sc, rs);
            m[i] = nm;
#pragma unroll
            for (int j = 0; j < 4; j++) o[i][j] *= sc;
        }
        __syncthreads();   // everyone done reading K before P overwrite

        // write P into KP as [k][q]
#pragma unroll
        for (int j = 0; j < 4; j++) {
            *(float4*)&KP[(c0 + j) * 64 + q0] =
                make_float4(s[0][j], s[1][j], s[2][j], s[3][j]);
        }
        __syncthreads();

        // O += P V
#pragma unroll 8
        for (int k = 0; k < 64; k++) {
            float4 pv = *(const float4*)&KP[k * 64 + q0];
            float4 vv = *(const float4*)&Vs[k * 64 + c0];
            float pr[4] = {pv.x, pv.y, pv.z, pv.w};
            float vr[4] = {vv.x, vv.y, vv.z, vv.w};
#pragma unroll
            for (int i = 0; i < 4; i++)
#pragma unroll
                for (int j = 0; j < 4; j++)
                    o[i][j] = fmaf(pr[i], vr[j], o[i][j]);
        }
        __syncthreads();   // done reading P/V before next tile load
    }

    // y[b][d][n] = O / l
    float inv[4];
#pragma unroll
    for (int i = 0; i < 4; i++) inv[i] = 1.0f / l[i];
    float* yo = d_y + (size_t)b * NCI * NN + qb;
#pragma unroll
    for (int j = 0; j < 4; j++) {
        float4 v = make_float4(o[0][j] * inv[0], o[1][j] * inv[1],
                               o[2][j] * inv[2], o[3][j] * inv[3]);
        *(float4*)&yo[(size_t)(c0 + j) * NN + q0] = v;
    }
}

// ---------------------------------------------------------------------------
// out[b][co][n] = sum_ci Ww[co][ci] * y[b][ci][n] + Wb[co] + x0[b][co][n]
// Static smem: ws[32][128] + ys[32][128] = 32KB, two ci-half passes.
// ---------------------------------------------------------------------------
__global__ void __launch_bounds__(256) out_kernel(
    const float* __restrict__ x0, const float* __restrict__ Ww,
    const float* __restrict__ Wb, float* __restrict__ out)
{
    __shared__ __align__(16) float ws[32 * 128]; // [ci_local][co]
    __shared__ __align__(16) float ys[32 * 128]; // [ci_local][p]

    int b = blockIdx.y;
    int n0 = blockIdx.x * 128;
    int t = threadIdx.x;
    int tx = t & 15, ty = t >> 4;
    int co0 = ty * 4, p0 = tx * 4;

    float acc[8][8];
#pragma unroll
    for (int i = 0; i < 8; i++)
#pragma unroll
        for (int j = 0; j < 8; j++) acc[i][j] = 0.0f;

    const float* yg = d_y + (size_t)b * NCI * NN + n0;

    for (int h = 0; h < 2; h++) {
        if (h) __syncthreads();
        for (int e = t; e < 128 * 32; e += 256) {
            int co = e >> 5, cil = e & 31;
            ws[cil * 128 + co] = Ww[co * NCI + h * 32 + cil];
        }
        for (int e = t; e < 32 * 128; e += 256) {
            int cil = e >> 7, p = e & 127;
            ys[cil * 128 + p] = yg[(size_t)(h * 32 + cil) * NN + p];
        }
        __syncthreads();
#pragma unroll 4
        for (int cil = 0; cil < 32; cil++) {
            float4 wa = *(const float4*)&ws[cil * 128 + co0];
            float4 wc = *(const float4*)&ws[cil * 128 + co0 + 64];
            float4 ya = *(const float4*)&ys[cil * 128 + p0];
            float4 yc = *(const float4*)&ys[cil * 128 + p0 + 64];
            float wr[8] = {wa.x, wa.y, wa.z, wa.w, wc.x, wc.y, wc.z, wc.w};
            float yr[8] = {ya.x, ya.y, ya.z, ya.w, yc.x, yc.y, yc.z, yc.w};
#pragma unroll
            for (int i = 0; i < 8; i++)
#pragma unroll
                for (int j = 0; j < 8; j++)
                    acc[i][j] = fmaf(wr[i], yr[j], acc[i][j]);
        }
    }

    const float* xb = x0 + (size_t)b * NC * NN + n0;
    float* ob = out + (size_t)b * NC * NN + n0;
#pragma unroll
    for (int ih = 0; ih < 2; ih++)
#pragma unroll
        for (int i = 0; i < 4; i++) {
            int co = co0 + ih * 64 + i;
            float bv = Wb[co];
            int ai = ih * 4 + i;
#pragma unroll
            for (int jh = 0; jh < 2; jh++) {
                int p = p0 + jh * 64;
                int aj = jh * 4;
                float4 xv = *(const float4*)&xb[(size_t)co * NN + p];
                float4 r = make_float4(acc[ai][aj + 0] + bv + xv.x,
                                       acc[ai][aj + 1] + bv + xv.y,
                                       acc[ai][aj + 2] + bv + xv.z,
                                       acc[ai][aj + 3] + bv + xv.w);
                *(float4*)&ob[(size_t)co * NN + p] = r;
            }
        }
}

extern "C" void kernel_launch(void* const* d_in, const int* in_sizes, int n_in,
                              void* d_out, int out_size)
{
    const float* x0   = (const float*)d_in[0];
    const float* x1   = (const float*)d_in[1];
    const float* g_w  = (const float*)d_in[2];
    const float* g_b  = (const float*)d_in[3];
    const float* th_w = (const float*)d_in[4];
    const float* th_b = (const float*)d_in[5];
    const float* ph_w = (const float*)d_in[6];
    const float* ph_b = (const float*)d_in[7];
    const float* W_w  = (const float*)d_in[8];
    const float* W_b  = (const float*)d_in[9];
    float* out = (float*)d_out;

    proj_kernel<<<dim3(NN / 128, NB, 3), 256>>>(x0, x1, th_w, th_b, ph_w, ph_b, g_w, g_b);
    attn_kernel<<<dim3(NN / 64, NB), 256>>>();
    out_kernel<<<dim3(NN / 128, NB), 256>>>(x0, W_w, W_b, out);
}

// round 8
// speedup vs baseline: 3.7676x; 3.7676x over previous
#include <cuda_runtime.h>
#include <cstdint>

#define NB 4
#define NC 128
#define NCI 64
#define NN 4096

// Scratch (device globals — no allocation allowed)
__device__ __align__(16) float d_theta[NB * NCI * NN]; // [b][ci][n]  (Q, d-major)
__device__ __align__(16) float d_phi[NB * NCI * NN];   // [b][ci][n]  (K, d-major)
__device__ __align__(16) float d_g[NB * NCI * NN];     // [b][ci][n]  (V, d-major)
__device__ __align__(16) float d_y[NB * NCI * NN];     // [b][ci][n]

// FFMA-only exp (MUFU would bottleneck for 67M exps).
__device__ __forceinline__ float fast_exp(float x) {
    x = fmaxf(x, -60.0f);
    float t = x * 1.4426950408889634f;
    float r = t + 12582912.0f;
    int   i = __float_as_int(r) - 0x4B400000;
    float f = t - (r - 12582912.0f);
    float p = 1.33336e-3f;
    p = fmaf(p, f, 9.61813e-3f);
    p = fmaf(p, f, 5.550411e-2f);
    p = fmaf(p, f, 2.4022651e-1f);
    p = fmaf(p, f, 6.9314718e-1f);
    p = fmaf(p, f, 1.0f);
    return __int_as_float(__float_as_int(p) + (i << 23));
}

__device__ __forceinline__ uint32_t cvt_tf32(float x) {
    uint32_t r;
    asm("cvt.rna.tf32.f32 %0, %1;" : "=r"(r) : "f"(x));
    return r;
}
__device__ __forceinline__ float cvt_tf32f(float x) {
    uint32_t r;
    asm("cvt.rna.tf32.f32 %0, %1;" : "=r"(r) : "f"(x));
    return __uint_as_float(r);
}

__device__ __forceinline__ void mma_tf32(float c[4], const uint32_t a[4],
                                         uint32_t b0, uint32_t b1) {
    asm volatile(
        "mma.sync.aligned.m16n8k8.row.col.f32.tf32.tf32.f32 "
        "{%0,%1,%2,%3}, {%4,%5,%6,%7}, {%8,%9}, {%0,%1,%2,%3};\n"
        : "+f"(c[0]), "+f"(c[1]), "+f"(c[2]), "+f"(c[3])
        : "r"(a[0]), "r"(a[1]), "r"(a[2]), "r"(a[3]), "r"(b0), "r"(b1));
}

// ---------------------------------------------------------------------------
// Projections: out[ci][n] = sum_c w[ci][c] * x[c][n] + b[ci]
// z=0: theta(x1); z=1: phi(x0); z=2: g(x0). All outputs [b][ci][n].
// ---------------------------------------------------------------------------
__global__ void __launch_bounds__(256) proj_kernel(
    const float* __restrict__ x0, const float* __restrict__ x1,
    const float* __restrict__ theta_w, const float* __restrict__ theta_b,
    const float* __restrict__ phi_w,   const float* __restrict__ phi_b,
    const float* __restrict__ g_w,     const float* __restrict__ g_b)
{
    __shared__ __align__(16) float ws[64 * 64];   // [c_local][ci]
    __shared__ __align__(16) float xs[64 * 128];  // [c_local][p]

    int b = blockIdx.y;
    int n0 = blockIdx.x * 128;
    int which = blockIdx.z;
    const float* w    = (which == 0) ? theta_w : ((which == 1) ? phi_w : g_w);
    const float* bias = (which == 0) ? theta_b : ((which == 1) ? phi_b : g_b);
    const float* src  = (which == 0) ? x1 : x0;

    int t = threadIdx.x;
    int tx = t & 15, ty = t >> 4;
    int ci0 = ty * 4, p0 = tx * 4;

    float acc[4][8];
#pragma unroll
    for (int i = 0; i < 4; i++)
#pragma unroll
        for (int j = 0; j < 8; j++) acc[i][j] = 0.0f;

    const float* xb = src + (size_t)b * NC * NN + n0;

    for (int h = 0; h < 2; h++) {
        if (h) __syncthreads();
        for (int e = t; e < 64 * 64; e += 256) {
            int ci = e >> 6, cl = e & 63;
            ws[cl * 64 + ci] = w[ci * NC + h * 64 + cl];
        }
        for (int e = t; e < 64 * 128; e += 256) {
            int cl = e >> 7, p = e & 127;
            xs[cl * 128 + p] = xb[(size_t)(h * 64 + cl) * NN + p];
        }
        __syncthreads();
#pragma unroll 4
        for (int cl = 0; cl < 64; cl++) {
            float4 wv = *(const float4*)&ws[cl * 64 + ci0];
            float4 xa = *(const float4*)&xs[cl * 128 + p0];
            float4 xc = *(const float4*)&xs[cl * 128 + p0 + 64];
            float wr[4] = {wv.x, wv.y, wv.z, wv.w};
            float xr[8] = {xa.x, xa.y, xa.z, xa.w, xc.x, xc.y, xc.z, xc.w};
#pragma unroll
            for (int i = 0; i < 4; i++)
#pragma unroll
                for (int j = 0; j < 8; j++)
                    acc[i][j] = fmaf(wr[i], xr[j], acc[i][j]);
        }
    }

    float* out = ((which == 0) ? d_theta : ((which == 1) ? d_phi : d_g))
                 + (size_t)b * NCI * NN + n0;
#pragma unroll
    for (int i = 0; i < 4; i++) {
        float bv = bias[ci0 + i];
        float4 v0 = make_float4(acc[i][0] + bv, acc[i][1] + bv,
                                acc[i][2] + bv, acc[i][3] + bv);
        float4 v1 = make_float4(acc[i][4] + bv, acc[i][5] + bv,
                                acc[i][6] + bv, acc[i][7] + bv);
        *(float4*)&out[(size_t)(ci0 + i) * NN + p0] = v0;
        *(float4*)&out[(size_t)(ci0 + i) * NN + p0 + 64] = v1;
    }
}

// ---------------------------------------------------------------------------
// Flash attention with tf32 mma.sync. One CTA = 64 queries, 4 warps (16 q
// each), 128 threads. Q fragments register-resident. K/V smem tiles [d][k]
// with XOR swizzle col ^= f(d)<<2, f(d) = ((d&3)<<1)|((d>>2)&1) —
// conflict-free for tile stores and all mma B-fragment gathers.
// P stays in registers: C-frag -> A-frag via 8 shuffles per 16x8 tile.
// ---------------------------------------------------------------------------
__global__ void __launch_bounds__(128) attn_kernel()
{
    __shared__ uint32_t Ks[64 * 64];
    __shared__ uint32_t Vs[64 * 64];

    int b = blockIdx.y;
    int qb = blockIdx.x * 64;
    int t = threadIdx.x;
    int w = t >> 5, lane = t & 31;
    int g = lane >> 2, j = lane & 3;

    const float* Qg = d_theta + (size_t)b * NCI * NN;
    const float* Kg = d_phi   + (size_t)b * NCI * NN;
    const float* Vg = d_g     + (size_t)b * NCI * NN;
    int q0 = qb + w * 16;

    // Q fragments: a-frags for all 8 k-steps (d = ks*8 .. ks*8+7)
    uint32_t qa[8][4];
#pragma unroll
    for (int ks = 0; ks < 8; ks++) {
        int d0 = ks * 8 + j;
        const float* Qp = Qg + (size_t)d0 * NN + q0 + g;
        qa[ks][0] = cvt_tf32(__ldg(Qp));
        qa[ks][1] = cvt_tf32(__ldg(Qp + 8));
        qa[ks][2] = cvt_tf32(__ldg(Qp + 4 * NN));
        qa[ks][3] = cvt_tf32(__ldg(Qp + 4 * NN + 8));
    }

    float o[8][4];
#pragma unroll
    for (int nt = 0; nt < 8; nt++)
#pragma unroll
        for (int i = 0; i < 4; i++) o[nt][i] = 0.0f;
    float m0 = -1e30f, m1 = -1e30f, l0 = 0.0f, l1 = 0.0f;

    // per-thread V-fragment swizzle key: d = nt*8+g -> f = ((g&3)<<1)|(g>>2)
    int fv = ((g & 3) << 1) | (g >> 2);

    for (int kb = 0; kb < NN; kb += 64) {
        // ---- load K,V tiles (tf32-convert at store) ----
#pragma unroll
        for (int e = t; e < 1024; e += 128) {
            int d = e >> 4, k4 = (e & 15) << 2;
            int f = ((d & 3) << 1) | ((d >> 2) & 1);
            int col = k4 ^ (f << 2);
            float4 kv = *(const float4*)(Kg + (size_t)d * NN + kb + k4);
            float4 vv = *(const float4*)(Vg + (size_t)d * NN + kb + k4);
            uint32_t* kp = &Ks[d * 64 + col];
            kp[0] = cvt_tf32(kv.x); kp[1] = cvt_tf32(kv.y);
            kp[2] = cvt_tf32(kv.z); kp[3] = cvt_tf32(kv.w);
            uint32_t* vp = &Vs[d * 64 + col];
            vp[0] = cvt_tf32(vv.x); vp[1] = cvt_tf32(vv.y);
            vp[2] = cvt_tf32(vv.z); vp[3] = cvt_tf32(vv.w);
        }
        __syncthreads();

        // ---- S = Q K^T : warp tile 16x64, 8 n-tiles x 8 k-steps ----
        float s[8][4];
#pragma unroll
        for (int nt = 0; nt < 8; nt++)
#pragma unroll
            for (int i = 0; i < 4; i++) s[nt][i] = 0.0f;

#pragma unroll
        for (int ks = 0; ks < 8; ks++) {
            int d0 = 8 * ks + j;
            int x0s = j << 3;           // f(d0)<<2 = (2j)<<2
#pragma unroll
            for (int nt = 0; nt < 8; nt++) {
                int kcol = nt * 8 + g;
                uint32_t b0 = Ks[d0 * 64 + (kcol ^ x0s)];
                uint32_t b1 = Ks[(d0 + 4) * 64 + ((kcol ^ x0s) ^ 4)];
                mma_tf32(s[nt], qa[ks], b0, b1);
            }
        }

        // ---- online softmax: thread owns rows g (regs 0,1) and g+8 (2,3) ----
        float t0 = -1e30f, t1 = -1e30f;
#pragma unroll
        for (int nt = 0; nt < 8; nt++) {
            t0 = fmaxf(t0, fmaxf(s[nt][0], s[nt][1]));
            t1 = fmaxf(t1, fmaxf(s[nt][2], s[nt][3]));
        }
        t0 = fmaxf(t0, __shfl_xor_sync(0xffffffffu, t0, 1));
        t0 = fmaxf(t0, __shfl_xor_sync(0xffffffffu, t0, 2));
        t1 = fmaxf(t1, __shfl_xor_sync(0xffffffffu, t1, 1));
        t1 = fmaxf(t1, __shfl_xor_sync(0xffffffffu, t1, 2));
        float nm0 = fmaxf(m0, t0), nm1 = fmaxf(m1, t1);
        float sc0 = fast_exp(m0 - nm0), sc1 = fast_exp(m1 - nm1);
        float rs0 = 0.0f, rs1 = 0.0f;
#pragma unroll
        for (int nt = 0; nt < 8; nt++) {
            s[nt][0] = cvt_tf32f(fast_exp(s[nt][0] - nm0));
            s[nt][1] = cvt_tf32f(fast_exp(s[nt][1] - nm0));
            s[nt][2] = cvt_tf32f(fast_exp(s[nt][2] - nm1));
            s[nt][3] = cvt_tf32f(fast_exp(s[nt][3] - nm1));
            rs0 += s[nt][0] + s[nt][1];
            rs1 += s[nt][2] + s[nt][3];
        }
        rs0 += __shfl_xor_sync(0xffffffffu, rs0, 1);
        rs0 += __shfl_xor_sync(0xffffffffu, rs0, 2);
        rs1 += __shfl_xor_sync(0xffffffffu, rs1, 1);
        rs1 += __shfl_xor_sync(0xffffffffu, rs1, 2);
        l0 = fmaf(l0, sc0, rs0);
        l1 = fmaf(l1, sc1, rs1);
        m0 = nm0; m1 = nm1;
#pragma unroll
        for (int nt = 0; nt < 8; nt++) {
            o[nt][0] *= sc0; o[nt][1] *= sc0;
            o[nt][2] *= sc1; o[nt][3] *= sc1;
        }

        // ---- O += P V : A-frag of P from C-frag via quad shuffles ----
        int src0 = (lane & ~3) | (j >> 1);
        int src2 = src0 + 2;
        bool odd = (j & 1);
#pragma unroll
        for (int ks = 0; ks < 8; ks++) {
            float c0 = s[ks][0], c1 = s[ks][1], c2 = s[ks][2], c3 = s[ks][3];
            float v00 = __shfl_sync(0xffffffffu, c0, src0);
            float v01 = __shfl_sync(0xffffffffu, c1, src0);
            float v10 = __shfl_sync(0xffffffffu, c2, src0);
            float v11 = __shfl_sync(0xffffffffu, c3, src0);
            float v20 = __shfl_sync(0xffffffffu, c0, src2);
            float v21 = __shfl_sync(0xffffffffu, c1, src2);
            float v30 = __shfl_sync(0xffffffffu, c2, src2);
            float v31 = __shfl_sync(0xffffffffu, c3, src2);
            uint32_t ap[4];
            ap[0] = __float_as_uint(odd ? v01 : v00);
            ap[1] = __float_as_uint(odd ? v11 : v10);
            ap[2] = __float_as_uint(odd ? v21 : v20);
            ap[3] = __float_as_uint(odd ? v31 : v30);
            int col0 = (8 * ks + j) ^ (fv << 2);
            int col1 = col0 ^ 4;
#pragma unroll
            for (int nt = 0; nt < 8; nt++) {
                uint32_t b0 = Vs[(nt * 8 + g) * 64 + col0];
                uint32_t b1 = Vs[(nt * 8 + g) * 64 + col1];
                mma_tf32(o[nt], ap, b0, b1);
            }
        }
        __syncthreads();
    }

    // ---- epilogue: y[b][d][n] = O / l ----
    float inv0 = 1.0f / l0, inv1 = 1.0f / l1;
    float* yo = d_y + (size_t)b * NCI * NN;
    int qg0 = q0 + g, qg1 = q0 + g + 8;
#pragma unroll
    for (int nt = 0; nt < 8; nt++) {
        int d0 = nt * 8 + 2 * j;
        yo[(size_t)d0 * NN + qg0]       = o[nt][0] * inv0;
        yo[(size_t)(d0 + 1) * NN + qg0] = o[nt][1] * inv0;
        yo[(size_t)d0 * NN + qg1]       = o[nt][2] * inv1;
        yo[(size_t)(d0 + 1) * NN + qg1] = o[nt][3] * inv1;
    }
}

// ---------------------------------------------------------------------------
// out[b][co][n] = sum_ci Ww[co][ci] * y[b][ci][n] + Wb[co] + x0[b][co][n]
// ---------------------------------------------------------------------------
__global__ void __launch_bounds__(256) out_kernel(
    const float* __restrict__ x0, const float* __restrict__ Ww,
    const float* __restrict__ Wb, float* __restrict__ out)
{
    __shared__ __align__(16) float ws[32 * 128]; // [ci_local][co]
    __shared__ __align__(16) float ys[32 * 128]; // [ci_local][p]

    int b = blockIdx.y;
    int n0 = blockIdx.x * 128;
    int t = threadIdx.x;
    int tx = t & 15, ty = t >> 4;
    int co0 = ty * 4, p0 = tx * 4;

    float acc[8][8];
#pragma unroll
    for (int i = 0; i < 8; i++)
#pragma unroll
        for (int j = 0; j < 8; j++) acc[i][j] = 0.0f;

    const float* yg = d_y + (size_t)b * NCI * NN + n0;

    for (int h = 0; h < 2; h++) {
        if (h) __syncthreads();
        for (int e = t; e < 128 * 32; e += 256) {
            int co = e >> 5, cil = e & 31;
            ws[cil * 128 + co] = Ww[co * NCI + h * 32 + cil];
        }
        for (int e = t; e < 32 * 128; e += 256) {
            int cil = e >> 7, p = e & 127;
            ys[cil * 128 + p] = yg[(size_t)(h * 32 + cil) * NN + p];
        }
        __syncthreads();
#pragma unroll 4
        for (int cil = 0; cil < 32; cil++) {
            float4 wa = *(const float4*)&ws[cil * 128 + co0];
            float4 wc = *(const float4*)&ws[cil * 128 + co0 + 64];
            float4 ya = *(const float4*)&ys[cil * 128 + p0];
            float4 yc = *(const float4*)&ys[cil * 128 + p0 + 64];
            float wr[8] = {wa.x, wa.y, wa.z, wa.w, wc.x, wc.y, wc.z, wc.w};
            float yr[8] = {ya.x, ya.y, ya.z, ya.w, yc.x, yc.y, yc.z, yc.w};
#pragma unroll
            for (int i = 0; i < 8; i++)
#pragma unroll
                for (int j = 0; j < 8; j++)
                    acc[i][j] = fmaf(wr[i], yr[j], acc[i][j]);
        }
    }

    const float* xb = x0 + (size_t)b * NC * NN + n0;
    float* ob = out + (size_t)b * NC * NN + n0;
#pragma unroll
    for (int ih = 0; ih < 2; ih++)
#pragma unroll
        for (int i = 0; i < 4; i++) {
            int co = co0 + ih * 64 + i;
            float bv = Wb[co];
            int ai = ih * 4 + i;
#pragma unroll
            for (int jh = 0; jh < 2; jh++) {
                int p = p0 + jh * 64;
                int aj = jh * 4;
                float4 xv = *(const float4*)&xb[(size_t)co * NN + p];
                float4 r = make_float4(acc[ai][aj + 0] + bv + xv.x,
                                       acc[ai][aj + 1] + bv + xv.y,
                                       acc[ai][aj + 2] + bv + xv.z,
                                       acc[ai][aj + 3] + bv + xv.w);
                *(float4*)&ob[(size_t)co * NN + p] = r;
            }
        }
}

extern "C" void kernel_launch(void* const* d_in, const int* in_sizes, int n_in,
                              void* d_out, int out_size)
{
    const float* x0   = (const float*)d_in[0];
    const float* x1   = (const float*)d_in[1];
    const float* g_w  = (const float*)d_in[2];
    const float* g_b  = (const float*)d_in[3];
    const float* th_w = (const float*)d_in[4];
    const float* th_b = (const float*)d_in[5];
    const float* ph_w = (const float*)d_in[6];
    const float* ph_b = (const float*)d_in[7];
    const float* W_w  = (const float*)d_in[8];
    const float* W_b  = (const float*)d_in[9];
    float* out = (float*)d_out;

    proj_kernel<<<dim3(NN / 128, NB, 3), 256>>>(x0, x1, th_w, th_b, ph_w, ph_b, g_w, g_b);
    attn_kernel<<<dim3(NN / 64, NB), 128>>>();
    out_kernel<<<dim3(NN / 128, NB), 256>>>(x0, W_w, W_b, out);
}

// round 9
// speedup vs baseline: 6.9878x; 1.8547x over previous
#include <cuda_runtime.h>
#include <cuda_bf16.h>
#include <cstdint>

#define NB 4
#define NC 128
#define NCI 64
#define NN 4096

// Scratch (device globals — no allocation allowed)
__device__ __align__(16) __nv_bfloat16 d_theta[NB * NN * NCI]; // [b][n][ci] (Q)
__device__ __align__(16) __nv_bfloat16 d_phi[NB * NN * NCI];   // [b][n][ci] (K)
__device__ __align__(16) __nv_bfloat16 d_g[NB * NN * NCI];     // [b][n][ci] (V)
__device__ __align__(16) float d_y[NB * NCI * NN];             // [b][ci][n] fp32

// FFMA-only exp (MUFU would bottleneck for 67M exps).
__device__ __forceinline__ float fast_exp(float x) {
    x = fmaxf(x, -60.0f);
    float t = x * 1.4426950408889634f;
    float r = t + 12582912.0f;
    int   i = __float_as_int(r) - 0x4B400000;
    float f = t - (r - 12582912.0f);
    float p = 1.33336e-3f;
    p = fmaf(p, f, 9.61813e-3f);
    p = fmaf(p, f, 5.550411e-2f);
    p = fmaf(p, f, 2.4022651e-1f);
    p = fmaf(p, f, 6.9314718e-1f);
    p = fmaf(p, f, 1.0f);
    return __int_as_float(__float_as_int(p) + (i << 23));
}

__device__ __forceinline__ uint32_t pack_bf16(float lo, float hi) {
    __nv_bfloat162 h = __floats2bfloat162_rn(lo, hi);
    return *(uint32_t*)&h;
}

__device__ __forceinline__ uint32_t smem_u32(const void* p) {
    return (uint32_t)__cvta_generic_to_shared(p);
}

__device__ __forceinline__ void mma_bf16(float c[4], const uint32_t a[4],
                                         uint32_t b0, uint32_t b1) {
    asm volatile(
        "mma.sync.aligned.m16n8k16.row.col.f32.bf16.bf16.f32 "
        "{%0,%1,%2,%3}, {%4,%5,%6,%7}, {%8,%9}, {%0,%1,%2,%3};\n"
        : "+f"(c[0]), "+f"(c[1]), "+f"(c[2]), "+f"(c[3])
        : "r"(a[0]), "r"(a[1]), "r"(a[2]), "r"(a[3]), "r"(b0), "r"(b1));
}

__device__ __forceinline__ void ldsm_x4(uint32_t r[4], uint32_t addr) {
    asm volatile("ldmatrix.sync.aligned.m8n8.x4.shared.b16 {%0,%1,%2,%3}, [%4];"
                 : "=r"(r[0]), "=r"(r[1]), "=r"(r[2]), "=r"(r[3]) : "r"(addr));
}
__device__ __forceinline__ void ldsm_x4_t(uint32_t r[4], uint32_t addr) {
    asm volatile("ldmatrix.sync.aligned.m8n8.x4.trans.shared.b16 {%0,%1,%2,%3}, [%4];"
                 : "=r"(r[0]), "=r"(r[1]), "=r"(r[2]), "=r"(r[3]) : "r"(addr));
}

// cp.async one 64x64-bf16 tile (64 rows x 128B) into swizzled smem
__device__ __forceinline__ void load_tile_async(uint32_t dst,
                                                const __nv_bfloat16* src, int t) {
#pragma unroll
    for (int e = t; e < 512; e += 128) {
        int row = e >> 3, chunk = e & 7;
        uint32_t d = dst + row * 128 + ((chunk ^ (row & 7)) << 4);
        const void* s = (const uint8_t*)(src + (size_t)row * NCI) + chunk * 16;
        asm volatile("cp.async.cg.shared.global [%0], [%1], 16;\n" :: "r"(d), "l"(s));
    }
}

// ---------------------------------------------------------------------------
// Projections: out[n][ci] = sum_c w[ci][c] * x[c][n] + b[ci]   (bf16 output)
// z=0: theta(x1); z=1: phi(x0); z=2: g(x0).
// ---------------------------------------------------------------------------
__global__ void __launch_bounds__(256) proj_kernel(
    const float* __restrict__ x0, const float* __restrict__ x1,
    const float* __restrict__ theta_w, const float* __restrict__ theta_b,
    const float* __restrict__ phi_w,   const float* __restrict__ phi_b,
    const float* __restrict__ g_w,     const float* __restrict__ g_b)
{
    __shared__ __align__(16) float ws[64 * 64];   // [c_local][ci]
    __shared__ __align__(16) float xs[64 * 128];  // [c_local][p]

    int b = blockIdx.y;
    int n0 = blockIdx.x * 128;
    int which = blockIdx.z;
    const float* w    = (which == 0) ? theta_w : ((which == 1) ? phi_w : g_w);
    const float* bias = (which == 0) ? theta_b : ((which == 1) ? phi_b : g_b);
    const float* src  = (which == 0) ? x1 : x0;

    int t = threadIdx.x;
    int tx = t & 15, ty = t >> 4;
    int ci0 = ty * 4, p0 = tx * 4;

    float acc[4][8];
#pragma unroll
    for (int i = 0; i < 4; i++)
#pragma unroll
        for (int j = 0; j < 8; j++) acc[i][j] = 0.0f;

    const float* xb = src + (size_t)b * NC * NN + n0;

    for (int h = 0; h < 2; h++) {
        if (h) __syncthreads();
        for (int e = t; e < 64 * 64; e += 256) {
            int ci = e >> 6, cl = e & 63;
            ws[cl * 64 + ci] = w[ci * NC + h * 64 + cl];
        }
        for (int e = t; e < 64 * 128; e += 256) {
            int cl = e >> 7, p = e & 127;
            xs[cl * 128 + p] = xb[(size_t)(h * 64 + cl) * NN + p];
        }
        __syncthreads();
#pragma unroll 4
        for (int cl = 0; cl < 64; cl++) {
            float4 wv = *(const float4*)&ws[cl * 64 + ci0];
            float4 xa = *(const float4*)&xs[cl * 128 + p0];
            float4 xc = *(const float4*)&xs[cl * 128 + p0 + 64];
            float wr[4] = {wv.x, wv.y, wv.z, wv.w};
            float xr[8] = {xa.x, xa.y, xa.z, xa.w, xc.x, xc.y, xc.z, xc.w};
#pragma unroll
            for (int i = 0; i < 4; i++)
#pragma unroll
                for (int j = 0; j < 8; j++)
                    acc[i][j] = fmaf(wr[i], xr[j], acc[i][j]);
        }
    }

    __nv_bfloat16* out = ((which == 0) ? d_theta : ((which == 1) ? d_phi : d_g))
                         + (size_t)b * NN * NCI + (size_t)n0 * NCI;
    float b0v = bias[ci0], b1v = bias[ci0 + 1], b2v = bias[ci0 + 2], b3v = bias[ci0 + 3];
#pragma unroll
    for (int jj = 0; jj < 8; jj++) {
        int p = (jj < 4) ? (p0 + jj) : (p0 + 60 + jj);
        uint2 v;
        v.x = pack_bf16(acc[0][jj] + b0v, acc[1][jj] + b1v);
        v.y = pack_bf16(acc[2][jj] + b2v, acc[3][jj] + b3v);
        *(uint2*)&out[(size_t)p * NCI + ci0] = v;
    }
}

// ---------------------------------------------------------------------------
// Flash attention, bf16 m16n8k16 mma. One CTA = 64 queries, 4 warps, 128 thr.
// Q a-frags register-resident (via ldmatrix from staged smem).
// K tile [kidx][d], V tile [kidx][d] in smem, 128B rows, chunk^(row&7) swizzle.
// S B-frags: ldmatrix.x4; V B-frags: ldmatrix.x4.trans.
// P A-frags = packed S C-frags (no shuffles). cp.async double buffering.
// ---------------------------------------------------------------------------
__global__ void __launch_bounds__(128) attn_kernel()
{
    __shared__ __align__(16) uint8_t Qsm[64 * 128];
    __shared__ __align__(16) uint8_t Ksm[2][64 * 128];
    __shared__ __align__(16) uint8_t Vsm[2][64 * 128];

    int b = blockIdx.y;
    int qb = blockIdx.x * 64;
    int t = threadIdx.x;
    int w = t >> 5, lane = t & 31;
    int g = lane >> 2, j = lane & 3;
    int sel = lane >> 3, l7 = lane & 7;

    const __nv_bfloat16* Qg = d_theta + (size_t)b * NN * NCI + (size_t)qb * NCI;
    const __nv_bfloat16* Kg = d_phi   + (size_t)b * NN * NCI;
    const __nv_bfloat16* Vg = d_g     + (size_t)b * NN * NCI;

    uint32_t smQ  = smem_u32(Qsm);
    uint32_t smK0 = smem_u32(Ksm[0]), smK1 = smem_u32(Ksm[1]);
    uint32_t smV0 = smem_u32(Vsm[0]), smV1 = smem_u32(Vsm[1]);

    // prologue: start tile-0 K/V loads
    load_tile_async(smK0, Kg, t);
    load_tile_async(smV0, Vg, t);
    asm volatile("cp.async.commit_group;\n");

    // stage Q tile (overlaps with the cp.async above)
#pragma unroll
    for (int e = t; e < 512; e += 128) {
        int row = e >> 3, chunk = e & 7;
        uint4 v = *(const uint4*)((const uint8_t*)(Qg + (size_t)row * NCI) + chunk * 16);
        *(uint4*)&Qsm[row * 128 + ((chunk ^ (row & 7)) << 4)] = v;
    }
    __syncthreads();

    // Q a-frags for 4 k-steps (d = 16*ks .. 16*ks+15)
    uint32_t qa[4][4];
#pragma unroll
    for (int ks = 0; ks < 4; ks++) {
        int row = w * 16 + ((sel & 1) << 3) + l7;
        int chunk = 2 * ks + (sel >> 1);
        ldsm_x4(qa[ks], smQ + row * 128 + ((chunk ^ (row & 7)) << 4));
    }

    float o[8][4];
#pragma unroll
    for (int nt = 0; nt < 8; nt++)
#pragma unroll
        for (int i = 0; i < 4; i++) o[nt][i] = 0.0f;
    float m0 = -1e30f, m1 = -1e30f, l0 = 0.0f, l1 = 0.0f;

    for (int it = 0; it < NN / 64; it++) {
        uint32_t smKb = (it & 1) ? smK1 : smK0;
        uint32_t smVb = (it & 1) ? smV1 : smV0;
        if (it + 1 < NN / 64) {
            uint32_t smKn = (it & 1) ? smK0 : smK1;
            uint32_t smVn = (it & 1) ? smV0 : smV1;
            load_tile_async(smKn, Kg + (size_t)(it + 1) * 64 * NCI, t);
            load_tile_async(smVn, Vg + (size_t)(it + 1) * 64 * NCI, t);
            asm volatile("cp.async.commit_group;\n");
            asm volatile("cp.async.wait_group 1;\n");
        } else {
            asm volatile("cp.async.wait_group 0;\n");
        }
        __syncthreads();

        // ---- S = Q K^T ----
        float s[8][4];
#pragma unroll
        for (int nt = 0; nt < 8; nt++)
#pragma unroll
            for (int i = 0; i < 4; i++) s[nt][i] = 0.0f;

#pragma unroll
        for (int ks = 0; ks < 4; ks++) {
#pragma unroll
            for (int ntp = 0; ntp < 4; ntp++) {
                int row = ntp * 16 + ((sel >> 1) << 3) + l7;
                int chunk = 2 * ks + (sel & 1);
                uint32_t r[4];
                ldsm_x4(r, smKb + row * 128 + ((chunk ^ (row & 7)) << 4));
                mma_bf16(s[2 * ntp], qa[ks], r[0], r[1]);
                mma_bf16(s[2 * ntp + 1], qa[ks], r[2], r[3]);
            }
        }

        // ---- online softmax: rows g (regs 0,1) and g+8 (regs 2,3) ----
        float t0 = -1e30f, t1 = -1e30f;
#pragma unroll
        for (int nt = 0; nt < 8; nt++) {
            t0 = fmaxf(t0, fmaxf(s[nt][0], s[nt][1]));
            t1 = fmaxf(t1, fmaxf(s[nt][2], s[nt][3]));
        }
        t0 = fmaxf(t0, __shfl_xor_sync(0xffffffffu, t0, 1));
        t0 = fmaxf(t0, __shfl_xor_sync(0xffffffffu, t0, 2));
        t1 = fmaxf(t1, __shfl_xor_sync(0xffffffffu, t1, 1));
        t1 = fmaxf(t1, __shfl_xor_sync(0xffffffffu, t1, 2));
        float nm0 = fmaxf(m0, t0), nm1 = fmaxf(m1, t1);
        float sc0 = fast_exp(m0 - nm0), sc1 = fast_exp(m1 - nm1);
        float rs0 = 0.0f, rs1 = 0.0f;
#pragma unroll
        for (int nt = 0; nt < 8; nt++) {
            s[nt][0] = fast_exp(s[nt][0] - nm0);
            s[nt][1] = fast_exp(s[nt][1] - nm0);
            s[nt][2] = fast_exp(s[nt][2] - nm1);
            s[nt][3] = fast_exp(s[nt][3] - nm1);
            rs0 += s[nt][0] + s[nt][1];
            rs1 += s[nt][2] + s[nt][3];
        }
        rs0 += __shfl_xor_sync(0xffffffffu, rs0, 1);
        rs0 += __shfl_xor_sync(0xffffffffu, rs0, 2);
        rs1 += __shfl_xor_sync(0xffffffffu, rs1, 1);
        rs1 += __shfl_xor_sync(0xffffffffu, rs1, 2);
        l0 = fmaf(l0, sc0, rs0);
        l1 = fmaf(l1, sc1, rs1);
        m0 = nm0; m1 = nm1;
#pragma unroll
        for (int nt = 0; nt < 8; nt++) {
            o[nt][0] *= sc0; o[nt][1] *= sc0;
            o[nt][2] *= sc1; o[nt][3] *= sc1;
        }

        // ---- O += P V : P A-frags = packed C-frags ----
#pragma unroll
        for (int ks = 0; ks < 4; ks++) {
            uint32_t ap[4];
            ap[0] = pack_bf16(s[2 * ks][0], s[2 * ks][1]);
            ap[1] = pack_bf16(s[2 * ks][2], s[2 * ks][3]);
            ap[2] = pack_bf16(s[2 * ks + 1][0], s[2 * ks + 1][1]);
            ap[3] = pack_bf16(s[2 * ks + 1][2], s[2 * ks + 1][3]);
#pragma unroll
            for (int ntp = 0; ntp < 4; ntp++) {
                int row = 16 * ks + ((sel & 1) << 3) + l7;
                int chunk = 2 * ntp + (sel >> 1);
                uint32_t r[4];
                ldsm_x4_t(r, smVb + row * 128 + ((chunk ^ (row & 7)) << 4));
                mma_bf16(o[2 * ntp], ap, r[0], r[1]);
                mma_bf16(o[2 * ntp + 1], ap, r[2], r[3]);
            }
        }
        __syncthreads();
    }

    // ---- epilogue: y[b][d][n] = O / l   (fp32, [ci][n]) ----
    float inv0 = 1.0f / l0, inv1 = 1.0f / l1;
    float* yo = d_y + (size_t)b * NCI * NN;
    int q0 = qb + w * 16;
    int qg0 = q0 + g, qg1 = q0 + g + 8;
#pragma unroll
    for (int nt = 0; nt < 8; nt++) {
        int d0 = nt * 8 + 2 * j;
        yo[(size_t)d0 * NN + qg0]       = o[nt][0] * inv0;
        yo[(size_t)(d0 + 1) * NN + qg0] = o[nt][1] * inv0;
        yo[(size_t)d0 * NN + qg1]       = o[nt][2] * inv1;
        yo[(size_t)(d0 + 1) * NN + qg1] = o[nt][3] * inv1;
    }
}

// ---------------------------------------------------------------------------
// out[b][co][n] = sum_ci Ww[co][ci] * y[b][ci][n] + Wb[co] + x0[b][co][n]
// ---------------------------------------------------------------------------
__global__ void __launch_bounds__(256) out_kernel(
    const float* __restrict__ x0, const float* __restrict__ Ww,
    const float* __restrict__ Wb, float* __restrict__ out)
{
    __shared__ __align__(16) float ws[32 * 128]; // [ci_local][co]
    __shared__ __align__(16) float ys[32 * 128]; // [ci_local][p]

    int b = blockIdx.y;
    int n0 = blockIdx.x * 128;
    int t = threadIdx.x;
    int tx = t & 15, ty = t >> 4;
    int co0 = ty * 4, p0 = tx * 4;

    float acc[8][8];
#pragma unroll
    for (int i = 0; i < 8; i++)
#pragma unroll
        for (int j = 0; j < 8; j++) acc[i][j] = 0.0f;

    const float* yg = d_y + (size_t)b * NCI * NN + n0;

    for (int h = 0; h < 2; h++) {
        if (h) __syncthreads();
        for (int e = t; e < 128 * 32; e += 256) {
            int co = e >> 5, cil = e & 31;
            ws[cil * 128 + co] = Ww[co * NCI + h * 32 + cil];
        }
        for (int e = t; e < 32 * 128; e += 256) {
            int cil = e >> 7, p = e & 127;
            ys[cil * 128 + p] = yg[(size_t)(h * 32 + cil) * NN + p];
        }
        __syncthreads();
#pragma unroll 4
        for (int cil = 0; cil < 32; cil++) {
            float4 wa = *(const float4*)&ws[cil * 128 + co0];
            float4 wc = *(const float4*)&ws[cil * 128 + co0 + 64];
            float4 ya = *(const float4*)&ys[cil * 128 + p0];
            float4 yc = *(const float4*)&ys[cil * 128 + p0 + 64];
            float wr[8] = {wa.x, wa.y, wa.z, wa.w, wc.x, wc.y, wc.z, wc.w};
            float yr[8] = {ya.x, ya.y, ya.z, ya.w, yc.x, yc.y, yc.z, yc.w};
#pragma unroll
            for (int i = 0; i < 8; i++)
#pragma unroll
                for (int j = 0; j < 8; j++)
                    acc[i][j] = fmaf(wr[i], yr[j], acc[i][j]);
        }
    }

    const float* xb = x0 + (size_t)b * NC * NN + n0;
    float* ob = out + (size_t)b * NC * NN + n0;
#pragma unroll
    for (int ih = 0; ih < 2; ih++)
#pragma unroll
        for (int i = 0; i < 4; i++) {
            int co = co0 + ih * 64 + i;
            float bv = Wb[co];
            int ai = ih * 4 + i;
#pragma unroll
            for (int jh = 0; jh < 2; jh++) {
                int p = p0 + jh * 64;
                int aj = jh * 4;
                float4 xv = *(const float4*)&xb[(size_t)co * NN + p];
                float4 r = make_float4(acc[ai][aj + 0] + bv + xv.x,
                                       acc[ai][aj + 1] + bv + xv.y,
                                       acc[ai][aj + 2] + bv + xv.z,
                                       acc[ai][aj + 3] + bv + xv.w);
                *(float4*)&ob[(size_t)co * NN + p] = r;
            }
        }
}

extern "C" void kernel_launch(void* const* d_in, const int* in_sizes, int n_in,
                              void* d_out, int out_size)
{
    const float* x0   = (const float*)d_in[0];
    const float* x1   = (const float*)d_in[1];
    const float* g_w  = (const float*)d_in[2];
    const float* g_b  = (const float*)d_in[3];
    const float* th_w = (const float*)d_in[4];
    const float* th_b = (const float*)d_in[5];
    const float* ph_w = (const float*)d_in[6];
    const float* ph_b = (const float*)d_in[7];
    const float* W_w  = (const float*)d_in[8];
    const float* W_b  = (const float*)d_in[9];
    float* out = (float*)d_out;

    proj_kernel<<<dim3(NN / 128, NB, 3), 256>>>(x0, x1, th_w, th_b, ph_w, ph_b, g_w, g_b);
    attn_kernel<<<dim3(NN / 64, NB), 128>>>();
    out_kernel<<<dim3(NN / 128, NB), 256>>>(x0, W_w, W_b, out);
}